// round 8
// baseline (speedup 1.0000x reference)
#include <cuda_runtime.h>
#include <cuda_bf16.h>

// AdderVDSR collapses analytically (established R0-R2, rel_err 1.2e-7):
//   relu(adder_conv) == 0 exactly after block 1, so all 16 adder blocks emit
//   zeros and  out[b,c] = out_b[c] + pixel_shuffle(conv3x3(x,up_w)+up_b, 2).
//
// R8 = R4's winning shape (1 float4 out/thread, 98K threads) with the weight
// fetch turned into a 16x LDG.128 burst (MLP 16, one L2 round-trip) instead
// of R4's ~54 re-materialized scalars / R6's 27 serial LDG.64 prologue.
// up_w + o0*27 is only 8B-aligned; we load an aligned 64-float superset and
// select via a warp-uniform branch on shift s in {0,2} (indices compile-time
// in both arms -> no local-memory spill, no divergence).

__global__ __launch_bounds__(128, 1) void adder_vdsr_collapsed(
    const float* __restrict__ x,      // [2,3,128,128]
    const float* __restrict__ up_w,   // [12,3,3,3]
    const float* __restrict__ up_b,   // [12]
    const float* __restrict__ out_b,  // [3]
    float* __restrict__ out)          // [2,3,256,256]
{
    const int tx = threadIdx.x;                 // 0..63 -> conv col pair 2tx
    const int ty = threadIdx.y;                 // 0..1
    const int i  = blockIdx.y * 2 + ty;         // conv row 0..127
    const int z  = blockIdx.z;                  // 0..11
    const int b  = z / 6;
    const int cp = z - 6 * b;
    const int c  = cp >> 1;
    const int p  = cp & 1;
    const int o0 = 4 * c + 2 * p;
    const int j0 = 2 * tx;

    // ---- Weights: channels {o0, o0+1} = floats [o0*27, o0*27+54).
    // Aligned superset load: 16x float4 from (o0*27) & ~3, then shift-select.
    float wbuf[54];
    {
        const int base  = o0 * 27;
        const int abase = base & ~3;            // float4-aligned start
        const int s     = base & 3;             // 0 or 2 (warp-uniform)
        float4 wv[16];
        const float4* Wv = reinterpret_cast<const float4*>(up_w + abase);
        #pragma unroll
        for (int k = 0; k < 16; k++) wv[k] = __ldg(Wv + k);
        const float* wf = reinterpret_cast<const float*>(wv);
        if (s == 0) {
            #pragma unroll
            for (int k = 0; k < 54; k++) wbuf[k] = wf[k];
        } else {
            #pragma unroll
            for (int k = 0; k < 54; k++) wbuf[k] = wf[k + 2];
        }
    }
    const float2 bia = __ldg(reinterpret_cast<const float2*>(up_b + o0));
    const float  ob  = __ldg(out_b + c);

    float a00 = bia.x, a01 = bia.x;   // channel o0,   conv cols {j0, j0+1}
    float a10 = bia.y, a11 = bia.y;   // channel o0+1

    #pragma unroll
    for (int cin = 0; cin < 3; cin++) {
        const float* xp = x + (size_t)(b * 3 + cin) * 128 * 128;
        float v[3][4];                // rows ki, conv cols j0-1 .. j0+2
        #pragma unroll
        for (int ki = 0; ki < 3; ki++) {
            const int gi = i - 1 + ki;
            const bool rok = (gi >= 0) & (gi < 128);
            const float* rowp = xp + gi * 128;
            if (rok) {
                v[ki][0] = (tx > 0) ? __ldg(rowp + j0 - 1) : 0.0f;
                float2 m = __ldg(reinterpret_cast<const float2*>(rowp + j0));
                v[ki][1] = m.x;
                v[ki][2] = m.y;
                v[ki][3] = (tx < 63) ? __ldg(rowp + j0 + 2) : 0.0f;
            } else {
                v[ki][0] = v[ki][1] = v[ki][2] = v[ki][3] = 0.0f;
            }
        }
        #pragma unroll
        for (int ki = 0; ki < 3; ki++) {
            #pragma unroll
            for (int kj = 0; kj < 3; kj++) {
                const float w0 = wbuf[cin * 9 + ki * 3 + kj];       // ch o0
                const float w1 = wbuf[27 + cin * 9 + ki * 3 + kj];  // ch o0+1
                a00 = fmaf(v[ki][kj],     w0, a00);
                a10 = fmaf(v[ki][kj],     w1, a10);
                a01 = fmaf(v[ki][kj + 1], w0, a01);
                a11 = fmaf(v[ki][kj + 1], w1, a11);
            }
        }
    }

    // Pixel shuffle: conv col j -> out cols {2j, 2j+1}, channels {o0, o0+1}.
    // Thread covers out cols 4tx..4tx+3 of out-row (2i+p): one STG.128.
    float4 r = make_float4(a00 + ob, a10 + ob, a01 + ob, a11 + ob);
    float* row = out + ((size_t)(b * 3 + c) * 256 + (2 * i + p)) * 256;
    reinterpret_cast<float4*>(row)[tx] = r;
}

extern "C" void kernel_launch(void* const* d_in, const int* in_sizes, int n_in,
                              void* d_out, int out_size) {
    (void)in_sizes; (void)n_in; (void)out_size;
    const float* x     = (const float*)d_in[0];
    const float* up_w  = (const float*)d_in[1];
    const float* up_b  = (const float*)d_in[2];
    const float* out_b = (const float*)d_in[7];
    float* out = (float*)d_out;

    dim3 grid(1, 64, 12);   // 768 CTAs (5.2/SM): y = conv-row/2, z = b*6+c*2+p
    dim3 block(64, 2);      // 128 threads; 98K threads total (same as R4)
    adder_vdsr_collapsed<<<grid, block>>>(x, up_w, up_b, out_b, out);
}

// round 9
// speedup vs baseline: 1.0504x; 1.0504x over previous
#include <cuda_runtime.h>
#include <cuda_bf16.h>

// AdderVDSR collapses analytically (established R0-R2, rel_err 1.2e-7):
//   adder_conv = -(sum of 576 |.|) <= 0 strictly, relu(neg) == 0 exactly,
//   so all 16 adder blocks emit zeros and
//   out[b,c] = out_b[c] + pixel_shuffle(conv3x3(x, up_w) + up_b, r=2).
//
// R9 = R4 verbatim (best of 5 structural variants: ncu 6.27us, wall 6.62us).
// Five different memory-issue profiles all land at 6.3-6.9us ncu -> the
// kernel sits on the launch/ramp floor (T_ovh ~5000 cyc of ~7000 total);
// per-thread LDG restructuring cannot move it. Resubmitted for
// reproducibility per rigor.md before declaring convergence.
//
// Layout: one CTA owns (batch b, out color c, row parity p) -> conv channels
// {4c+2p, 4c+2p+1}; one thread emits one float4 of one output row (the
// pixel-shuffle interleave [o0@2j, o1@2j, o0@2j+1, o1@2j+1]).

__global__ __launch_bounds__(256) void adder_vdsr_collapsed(
    const float* __restrict__ x,      // [2,3,128,128]
    const float* __restrict__ up_w,   // [12,3,3,3]
    const float* __restrict__ up_b,   // [12]
    const float* __restrict__ out_b,  // [3]
    float* __restrict__ out)          // [2,3,256,256]
{
    const int tx = threadIdx.x;                 // 0..63  -> conv col pair 2tx
    const int ty = threadIdx.y;                 // 0..3
    const int i  = blockIdx.y * 4 + ty;         // conv row 0..127
    const int z  = blockIdx.z;                  // 0..11
    const int b  = z / 6;
    const int cp = z % 6;
    const int c  = cp >> 1;
    const int p  = cp & 1;
    const int o0 = 4 * c + 2 * p;

    // 54 CTA-uniform weights (uniform __ldg, L1 broadcast).
    float w0[27], w1[27];
    const float* W = up_w + o0 * 27;
    #pragma unroll
    for (int k = 0; k < 27; k++) {
        w0[k] = __ldg(W + k);
        w1[k] = __ldg(W + 27 + k);
    }
    const float bias0 = __ldg(up_b + o0);
    const float bias1 = __ldg(up_b + o0 + 1);
    const float ob    = __ldg(out_b + c);

    float a00 = bias0, a01 = bias0;   // channel o0, px {2tx, 2tx+1}
    float a10 = bias1, a11 = bias1;   // channel o1

    const int j0 = 2 * tx;

    #pragma unroll
    for (int cin = 0; cin < 3; cin++) {
        const float* xp = x + (size_t)(b * 3 + cin) * 128 * 128;
        float v[3][4];
        #pragma unroll
        for (int ki = 0; ki < 3; ki++) {
            const int gi = i - 1 + ki;
            const bool rok = (gi >= 0) & (gi < 128);
            #pragma unroll
            for (int kc = 0; kc < 4; kc++) {
                const int gj = j0 - 1 + kc;
                v[ki][kc] = (rok && gj >= 0 && gj < 128)
                          ? __ldg(xp + gi * 128 + gj) : 0.0f;
            }
        }
        #pragma unroll
        for (int ki = 0; ki < 3; ki++) {
            #pragma unroll
            for (int kj = 0; kj < 3; kj++) {
                const float wv0 = w0[cin * 9 + ki * 3 + kj];
                const float wv1 = w1[cin * 9 + ki * 3 + kj];
                a00 = fmaf(v[ki][kj],     wv0, a00);
                a10 = fmaf(v[ki][kj],     wv1, a10);
                a01 = fmaf(v[ki][kj + 1], wv0, a01);
                a11 = fmaf(v[ki][kj + 1], wv1, a11);
            }
        }
    }

    // Pixel-shuffle interleave: [o0@2tx, o1@2tx, o0@2tx+1, o1@2tx+1]
    float4 r = make_float4(a00 + ob, a10 + ob, a01 + ob, a11 + ob);
    float* row = out + ((size_t)(b * 3 + c) * 256 + (2 * i + p)) * 256;
    reinterpret_cast<float4*>(row)[tx] = r;
}

extern "C" void kernel_launch(void* const* d_in, const int* in_sizes, int n_in,
                              void* d_out, int out_size) {
    (void)in_sizes; (void)n_in; (void)out_size;
    const float* x     = (const float*)d_in[0];
    const float* up_w  = (const float*)d_in[1];
    const float* up_b  = (const float*)d_in[2];
    const float* out_b = (const float*)d_in[7];
    float* out = (float*)d_out;

    dim3 grid(1, 32, 12);   // 384 CTAs: y = i/4, z = b*6 + (c*2+p)
    dim3 block(64, 4);      // 256 threads; tx = conv-col pair, ty = row
    adder_vdsr_collapsed<<<grid, block>>>(x, up_w, up_b, out_b, out);
}

// round 11
// speedup vs baseline: 1.3029x; 1.2404x over previous
#include <cuda_runtime.h>
#include <cuda_bf16.h>

// AdderVDSR collapses analytically (established R0-R2, rel_err 1.2e-7):
//   adder_conv = -(sum of 576 |.|) < 0 strictly, relu(neg) == 0 exactly,
//   so all 16 adder blocks emit zeros and
//   out[b,c] = out_b[c] + pixel_shuffle(conv3x3(x, up_w) + up_b, r=2).
//
// R10: final grid-ramp test. Six variants all pinned at ncu 6.3-6.5us with
// every pipe <32% -> time is launch + CTA-dispatch ramp + tail. Only
// untested lever: CTA count. 192 CTAs (~1.3/SM, one clean wave), each
// thread emits TWO float4 outputs (rows i, i+4) reusing its 54 register
// weights. If flat vs R4 (384 CTAs), the kernel is terminal.

__global__ __launch_bounds__(256) void adder_vdsr_collapsed(
    const float* __restrict__ x,      // [2,3,128,128]
    const float* __restrict__ up_w,   // [12,3,3,3]
    const float* __restrict__ up_b,   // [12]
    const float* __restrict__ out_b,  // [3]
    float* __restrict__ out)          // [2,3,256,256]
{
    const int tx = threadIdx.x;                 // 0..63 -> conv col pair 2tx
    const int ty = threadIdx.y;                 // 0..3
    const int i0 = blockIdx.y * 8 + ty;         // rows i0 and i0+4
    const int z  = blockIdx.z;                  // 0..11
    const int b  = z / 6;
    const int cp = z % 6;
    const int c  = cp >> 1;
    const int p  = cp & 1;
    const int o0 = 4 * c + 2 * p;
    const int j0 = 2 * tx;

    // 54 CTA-uniform weights (uniform __ldg, L1 broadcast) - loaded once,
    // used for both output rows.
    float w0[27], w1[27];
    const float* W = up_w + o0 * 27;
    #pragma unroll
    for (int k = 0; k < 27; k++) {
        w0[k] = __ldg(W + k);
        w1[k] = __ldg(W + 27 + k);
    }
    const float bias0 = __ldg(up_b + o0);
    const float bias1 = __ldg(up_b + o0 + 1);
    const float ob    = __ldg(out_b + c);

    #pragma unroll
    for (int rr = 0; rr < 2; rr++) {
        const int i = i0 + 4 * rr;

        float a00 = bias0, a01 = bias0;   // channel o0,   px {2tx, 2tx+1}
        float a10 = bias1, a11 = bias1;   // channel o0+1

        #pragma unroll
        for (int cin = 0; cin < 3; cin++) {
            const float* xp = x + (size_t)(b * 3 + cin) * 128 * 128;
            float v[3][4];
            #pragma unroll
            for (int ki = 0; ki < 3; ki++) {
                const int gi = i - 1 + ki;
                const bool rok = (gi >= 0) & (gi < 128);
                #pragma unroll
                for (int kc = 0; kc < 4; kc++) {
                    const int gj = j0 - 1 + kc;
                    v[ki][kc] = (rok && gj >= 0 && gj < 128)
                              ? __ldg(xp + gi * 128 + gj) : 0.0f;
                }
            }
            #pragma unroll
            for (int ki = 0; ki < 3; ki++) {
                #pragma unroll
                for (int kj = 0; kj < 3; kj++) {
                    const float wv0 = w0[cin * 9 + ki * 3 + kj];
                    const float wv1 = w1[cin * 9 + ki * 3 + kj];
                    a00 = fmaf(v[ki][kj],     wv0, a00);
                    a10 = fmaf(v[ki][kj],     wv1, a10);
                    a01 = fmaf(v[ki][kj + 1], wv0, a01);
                    a11 = fmaf(v[ki][kj + 1], wv1, a11);
                }
            }
        }

        // Pixel shuffle: conv (i, 2tx..2tx+1) x ch {o0,o0+1} ->
        // out row (2i+p), cols 4tx..4tx+3, channel c. One STG.128.
        float4 r = make_float4(a00 + ob, a10 + ob, a01 + ob, a11 + ob);
        float* row = out + ((size_t)(b * 3 + c) * 256 + (2 * i + p)) * 256;
        reinterpret_cast<float4*>(row)[tx] = r;
    }
}

extern "C" void kernel_launch(void* const* d_in, const int* in_sizes, int n_in,
                              void* d_out, int out_size) {
    (void)in_sizes; (void)n_in; (void)out_size;
    const float* x     = (const float*)d_in[0];
    const float* up_w  = (const float*)d_in[1];
    const float* up_b  = (const float*)d_in[2];
    const float* out_b = (const float*)d_in[7];
    float* out = (float*)d_out;

    dim3 grid(1, 16, 12);   // 192 CTAs (~1.3/SM): y = row-block of 8, z = b,c,p
    dim3 block(64, 4);      // 256 threads; each thread does rows ty and ty+4
    adder_vdsr_collapsed<<<grid, block>>>(x, up_w, up_b, out_b, out);
}

// round 12
// speedup vs baseline: 1.3155x; 1.0097x over previous
#include <cuda_runtime.h>
#include <cuda_bf16.h>

// AdderVDSR collapses analytically (established R0-R2, rel_err 1.2e-7):
//   adder_conv = -(sum of 576 |.|) < 0 strictly, relu(neg) == 0 exactly,
//   so all 16 adder blocks emit zeros and
//   out[b,c] = out_b[c] + pixel_shuffle(conv3x3(x, up_w) + up_b, r=2).
//
// R11: continue the validated CTA-count/amortization direction.
//   R4  384 CTAs, 1 out/thread: 6.27-6.50us
//   R10 192 CTAs, 2 out/thread: 5.82us   <- first real move off the plateau
//   R11  96 CTAs, 4 out/thread: each CTA on its own SM, one clean dispatch
//        wave, weight prologue amortized 4x. Accumulators reused per rr
//        iteration so regs stay ~100.

__global__ __launch_bounds__(256) void adder_vdsr_collapsed(
    const float* __restrict__ x,      // [2,3,128,128]
    const float* __restrict__ up_w,   // [12,3,3,3]
    const float* __restrict__ up_b,   // [12]
    const float* __restrict__ out_b,  // [3]
    float* __restrict__ out)          // [2,3,256,256]
{
    const int tx = threadIdx.x;                 // 0..63 -> conv col pair 2tx
    const int ty = threadIdx.y;                 // 0..3
    const int i0 = blockIdx.y * 16 + ty;        // rows i0 + {0,4,8,12}
    const int z  = blockIdx.z;                  // 0..11
    const int b  = z / 6;
    const int cp = z % 6;
    const int c  = cp >> 1;
    const int p  = cp & 1;
    const int o0 = 4 * c + 2 * p;
    const int j0 = 2 * tx;

    // 54 CTA-uniform weights (uniform __ldg, L1 broadcast) - loaded once,
    // reused for all four output rows.
    float w0[27], w1[27];
    const float* W = up_w + o0 * 27;
    #pragma unroll
    for (int k = 0; k < 27; k++) {
        w0[k] = __ldg(W + k);
        w1[k] = __ldg(W + 27 + k);
    }
    const float bias0 = __ldg(up_b + o0);
    const float bias1 = __ldg(up_b + o0 + 1);
    const float ob    = __ldg(out_b + c);

    #pragma unroll
    for (int rr = 0; rr < 4; rr++) {
        const int i = i0 + 4 * rr;

        float a00 = bias0, a01 = bias0;   // channel o0,   px {2tx, 2tx+1}
        float a10 = bias1, a11 = bias1;   // channel o0+1

        #pragma unroll
        for (int cin = 0; cin < 3; cin++) {
            const float* xp = x + (size_t)(b * 3 + cin) * 128 * 128;
            float v[3][4];
            #pragma unroll
            for (int ki = 0; ki < 3; ki++) {
                const int gi = i - 1 + ki;
                const bool rok = (gi >= 0) & (gi < 128);
                #pragma unroll
                for (int kc = 0; kc < 4; kc++) {
                    const int gj = j0 - 1 + kc;
                    v[ki][kc] = (rok && gj >= 0 && gj < 128)
                              ? __ldg(xp + gi * 128 + gj) : 0.0f;
                }
            }
            #pragma unroll
            for (int ki = 0; ki < 3; ki++) {
                #pragma unroll
                for (int kj = 0; kj < 3; kj++) {
                    const float wv0 = w0[cin * 9 + ki * 3 + kj];
                    const float wv1 = w1[cin * 9 + ki * 3 + kj];
                    a00 = fmaf(v[ki][kj],     wv0, a00);
                    a10 = fmaf(v[ki][kj],     wv1, a10);
                    a01 = fmaf(v[ki][kj + 1], wv0, a01);
                    a11 = fmaf(v[ki][kj + 1], wv1, a11);
                }
            }
        }

        // Pixel shuffle: conv (i, 2tx..2tx+1) x ch {o0,o0+1} ->
        // out row (2i+p), cols 4tx..4tx+3, channel c. One STG.128.
        float4 r = make_float4(a00 + ob, a10 + ob, a01 + ob, a11 + ob);
        float* row = out + ((size_t)(b * 3 + c) * 256 + (2 * i + p)) * 256;
        reinterpret_cast<float4*>(row)[tx] = r;
    }
}

extern "C" void kernel_launch(void* const* d_in, const int* in_sizes, int n_in,
                              void* d_out, int out_size) {
    (void)in_sizes; (void)n_in; (void)out_size;
    const float* x     = (const float*)d_in[0];
    const float* up_w  = (const float*)d_in[1];
    const float* up_b  = (const float*)d_in[2];
    const float* out_b = (const float*)d_in[7];
    float* out = (float*)d_out;

    dim3 grid(1, 8, 12);    // 96 CTAs (one per SM): y = 16-row slab, z = b,c,p
    dim3 block(64, 4);      // 256 threads; each thread does 4 rows
    adder_vdsr_collapsed<<<grid, block>>>(x, up_w, up_b, out_b, out);
}